// round 1
// baseline (speedup 1.0000x reference)
#include <cuda_runtime.h>
#include <math.h>

// Problem constants (match reference setup_inputs)
#define S_TOK 2048
#define C_DIM 1024
#define E_NUM 16
#define H_DIM 256
#define HS_DIM 2048
#define G_NUM 4

// Scratch (device globals: no allocation allowed)
__device__ float g_combine[S_TOK * E_NUM];                     // 128 KB
__device__ float g_hw[(size_t)S_TOK * (E_NUM * H_DIM)];        // [S, 4096] 32 MB
__device__ float g_hs[(size_t)S_TOK * HS_DIM];                 // [S, 2048] 16 MB

// ---------------------------------------------------------------------------
// Router: one warp per token. Computes 16 logits, then grouped sigmoid top-k
// (group_limited_greedy) producing a dense combine[S, E] matrix.
// ---------------------------------------------------------------------------
__global__ void router_kernel(const float* __restrict__ x,
                              const float* __restrict__ rw,
                              const float* __restrict__ bias,
                              float* __restrict__ combine) {
    int warp_id = (int)((blockIdx.x * blockDim.x + threadIdx.x) >> 5);
    int lane = threadIdx.x & 31;
    if (warp_id >= S_TOK) return;
    const float* xr = x + (size_t)warp_id * C_DIM;
    float logits[E_NUM];
#pragma unroll
    for (int e = 0; e < E_NUM; e++) {
        const float* wr = rw + (size_t)e * C_DIM;
        float p = 0.f;
        for (int c = lane; c < C_DIM; c += 32) p = fmaf(xr[c], wr[c], p);
#pragma unroll
        for (int off = 16; off; off >>= 1) p += __shfl_xor_sync(0xffffffffu, p, off);
        logits[e] = p;
    }
    if (lane == 0) {
        float sc[E_NUM], sb[E_NUM];
#pragma unroll
        for (int e = 0; e < E_NUM; e++) {
            sc[e] = 1.f / (1.f + expf(-logits[e]));
            sb[e] = sc[e] + bias[e];
        }
        // group scores = sum of top-2 biased scores within each group of 4
        float gsc[G_NUM];
#pragma unroll
        for (int g = 0; g < G_NUM; g++) {
            float m1 = -1e30f, m2 = -1e30f;
#pragma unroll
            for (int j = 0; j < 4; j++) {
                float v = sb[g * 4 + j];
                if (v > m1) { m2 = m1; m1 = v; }
                else if (v > m2) { m2 = v; }
            }
            gsc[g] = m1 + m2;
        }
        // top-2 groups (strict > keeps lowest index on ties, matching jax)
        int bg0 = 0;
        for (int g = 1; g < G_NUM; g++) if (gsc[g] > gsc[bg0]) bg0 = g;
        int bg1 = -1;
        for (int g = 0; g < G_NUM; g++) {
            if (g == bg0) continue;
            if (bg1 < 0 || gsc[g] > gsc[bg1]) bg1 = g;
        }
        bool allowed[E_NUM];
#pragma unroll
        for (int e = 0; e < E_NUM; e++) {
            int g = e >> 2;
            allowed[e] = (g == bg0) || (g == bg1);
        }
        // top-4 experts among allowed, by biased score
        int idx[4];
        for (int k = 0; k < 4; k++) {
            int bi = 0; float bv = -1e30f;
            for (int e = 0; e < E_NUM; e++)
                if (allowed[e] && sb[e] > bv) { bv = sb[e]; bi = e; }
            allowed[bi] = false;
            idx[k] = bi;
        }
        // weights from UNBIASED sigmoid scores, renormalized
        float wsum = 1e-20f;
        for (int k = 0; k < 4; k++) wsum += sc[idx[k]];
        float row[E_NUM];
#pragma unroll
        for (int e = 0; e < E_NUM; e++) row[e] = 0.f;
        for (int k = 0; k < 4; k++) row[idx[k]] = sc[idx[k]] / wsum;
#pragma unroll
        for (int e = 0; e < E_NUM; e++) combine[(size_t)warp_id * E_NUM + e] = row[e];
    }
}

// ---------------------------------------------------------------------------
// Fused dual GEMM + SiLU: out[m, n] = silu(A@Bg)[m,n] * (A@Bu)[m,n] * scale
// A: [M, Kd] row-major.
// BT=false (routed): Bg/Bu are [E][Kd][Hper]; column n belongs to expert
//                    e = n / Hper; each 64-wide tile stays inside one expert.
// BT=true  (shared): Bg/Bu are [N, Kd] row-major (transposed load).
// SCALED: multiply row-wise by combine[m, e].
// Tiles: BM=128, BN=64, BK=16; 256 threads; 8x4 microtile per thread (x2 accum).
// ---------------------------------------------------------------------------
template <bool BT, bool SCALED>
__global__ __launch_bounds__(256)
void dual_gemm_silu_kernel(const float* __restrict__ A,
                           const float* __restrict__ Bg,
                           const float* __restrict__ Bu,
                           float* __restrict__ Cout,
                           const float* __restrict__ combine,
                           int M, int Kd, int N, int Hper) {
    const int BM = 128, BN = 64, BK = 16;
    __shared__ float As[BK][BM + 4];
    __shared__ float Bgs[BK][BN + 4];
    __shared__ float Bus[BK][BN + 4];

    int n0 = blockIdx.x * BN;
    int m0 = blockIdx.y * BM;
    int tid = threadIdx.x;
    int tx = tid & 15;   // column group: 4 cols
    int ty = tid >> 4;   // row group: 8 rows

    const float* bg;
    const float* bu;
    int ldb;
    if (BT) {
        bg = Bg + (size_t)n0 * Kd;
        bu = Bu + (size_t)n0 * Kd;
        ldb = Kd;
    } else {
        int e = n0 / Hper, h0 = n0 % Hper;
        size_t off = (size_t)e * Kd * Hper + h0;
        bg = Bg + off;
        bu = Bu + off;
        ldb = Hper;
    }

    float accg[8][4], accu[8][4];
#pragma unroll
    for (int i = 0; i < 8; i++)
#pragma unroll
        for (int j = 0; j < 4; j++) { accg[i][j] = 0.f; accu[i][j] = 0.f; }

    int arow = tid >> 2;   // 0..63
    int avec = tid & 3;    // 0..3

    for (int k0 = 0; k0 < Kd; k0 += BK) {
        // global loads into regs
        float4 a0 = *(const float4*)(A + (size_t)(m0 + arow) * Kd + k0 + avec * 4);
        float4 a1 = *(const float4*)(A + (size_t)(m0 + arow + 64) * Kd + k0 + avec * 4);
        float4 bg0, bu0;
        int brow = 0, bvec = 0;
        if (BT) {
            bg0 = *(const float4*)(bg + (size_t)arow * ldb + k0 + avec * 4);
            bu0 = *(const float4*)(bu + (size_t)arow * ldb + k0 + avec * 4);
        } else {
            brow = tid >> 4;   // 0..15
            bvec = tid & 15;   // 0..15
            bg0 = *(const float4*)(bg + (size_t)(k0 + brow) * ldb + bvec * 4);
            bu0 = *(const float4*)(bu + (size_t)(k0 + brow) * ldb + bvec * 4);
        }
        __syncthreads();
        // store A transposed
        As[avec * 4 + 0][arow] = a0.x;
        As[avec * 4 + 1][arow] = a0.y;
        As[avec * 4 + 2][arow] = a0.z;
        As[avec * 4 + 3][arow] = a0.w;
        As[avec * 4 + 0][arow + 64] = a1.x;
        As[avec * 4 + 1][arow + 64] = a1.y;
        As[avec * 4 + 2][arow + 64] = a1.z;
        As[avec * 4 + 3][arow + 64] = a1.w;
        if (BT) {
            Bgs[avec * 4 + 0][arow] = bg0.x;
            Bgs[avec * 4 + 1][arow] = bg0.y;
            Bgs[avec * 4 + 2][arow] = bg0.z;
            Bgs[avec * 4 + 3][arow] = bg0.w;
            Bus[avec * 4 + 0][arow] = bu0.x;
            Bus[avec * 4 + 1][arow] = bu0.y;
            Bus[avec * 4 + 2][arow] = bu0.z;
            Bus[avec * 4 + 3][arow] = bu0.w;
        } else {
            *(float4*)&Bgs[brow][bvec * 4] = bg0;
            *(float4*)&Bus[brow][bvec * 4] = bu0;
        }
        __syncthreads();
#pragma unroll
        for (int k = 0; k < BK; k++) {
            float4 af0 = *(const float4*)&As[k][ty * 8];
            float4 af1 = *(const float4*)&As[k][ty * 8 + 4];
            float4 bgf = *(const float4*)&Bgs[k][tx * 4];
            float4 buf = *(const float4*)&Bus[k][tx * 4];
            float ar[8] = {af0.x, af0.y, af0.z, af0.w, af1.x, af1.y, af1.z, af1.w};
            float gr[4] = {bgf.x, bgf.y, bgf.z, bgf.w};
            float ur[4] = {buf.x, buf.y, buf.z, buf.w};
#pragma unroll
            for (int i = 0; i < 8; i++) {
#pragma unroll
                for (int j = 0; j < 4; j++) {
                    accg[i][j] = fmaf(ar[i], gr[j], accg[i][j]);
                    accu[i][j] = fmaf(ar[i], ur[j], accu[i][j]);
                }
            }
        }
    }

    int e_idx = SCALED ? (n0 / Hper) : 0;
#pragma unroll
    for (int i = 0; i < 8; i++) {
        int row = m0 + ty * 8 + i;
        float scale = 1.f;
        if (SCALED) scale = combine[(size_t)row * E_NUM + e_idx];
        float4 o;
        float g, u;
        g = accg[i][0]; u = accu[i][0]; o.x = (g / (1.f + expf(-g))) * u * scale;
        g = accg[i][1]; u = accu[i][1]; o.y = (g / (1.f + expf(-g))) * u * scale;
        g = accg[i][2]; u = accu[i][2]; o.z = (g / (1.f + expf(-g))) * u * scale;
        g = accg[i][3]; u = accu[i][3]; o.w = (g / (1.f + expf(-g))) * u * scale;
        *(float4*)(Cout + (size_t)row * N + n0 + tx * 4) = o;
    }
}

// ---------------------------------------------------------------------------
// Single GEMM: C = A @ B (+ C if ACC).
// BT=false: B [Kd, N] row-major.  BT=true: B [N, Kd] row-major.
// Tiles: BM=128, BN=64, BK=16; 256 threads; 8x4 microtile.
// ---------------------------------------------------------------------------
template <bool BT, bool ACC>
__global__ __launch_bounds__(256)
void gemm_kernel(const float* __restrict__ A,
                 const float* __restrict__ B,
                 float* __restrict__ Cout,
                 int M, int Kd, int N) {
    const int BM = 128, BN = 64, BK = 16;
    __shared__ float As[BK][BM + 4];
    __shared__ float Bs[BK][BN + 4];

    int n0 = blockIdx.x * BN;
    int m0 = blockIdx.y * BM;
    int tid = threadIdx.x;
    int tx = tid & 15;
    int ty = tid >> 4;
    int ldb = BT ? Kd : N;

    float acc[8][4];
#pragma unroll
    for (int i = 0; i < 8; i++)
#pragma unroll
        for (int j = 0; j < 4; j++) acc[i][j] = 0.f;

    int arow = tid >> 2;
    int avec = tid & 3;

    for (int k0 = 0; k0 < Kd; k0 += BK) {
        float4 a0 = *(const float4*)(A + (size_t)(m0 + arow) * Kd + k0 + avec * 4);
        float4 a1 = *(const float4*)(A + (size_t)(m0 + arow + 64) * Kd + k0 + avec * 4);
        float4 b0;
        int brow = 0, bvec = 0;
        if (BT) {
            b0 = *(const float4*)(B + (size_t)(n0 + arow) * ldb + k0 + avec * 4);
        } else {
            brow = tid >> 4;
            bvec = tid & 15;
            b0 = *(const float4*)(B + (size_t)(k0 + brow) * ldb + n0 + bvec * 4);
        }
        __syncthreads();
        As[avec * 4 + 0][arow] = a0.x;
        As[avec * 4 + 1][arow] = a0.y;
        As[avec * 4 + 2][arow] = a0.z;
        As[avec * 4 + 3][arow] = a0.w;
        As[avec * 4 + 0][arow + 64] = a1.x;
        As[avec * 4 + 1][arow + 64] = a1.y;
        As[avec * 4 + 2][arow + 64] = a1.z;
        As[avec * 4 + 3][arow + 64] = a1.w;
        if (BT) {
            Bs[avec * 4 + 0][arow] = b0.x;
            Bs[avec * 4 + 1][arow] = b0.y;
            Bs[avec * 4 + 2][arow] = b0.z;
            Bs[avec * 4 + 3][arow] = b0.w;
        } else {
            *(float4*)&Bs[brow][bvec * 4] = b0;
        }
        __syncthreads();
#pragma unroll
        for (int k = 0; k < BK; k++) {
            float4 af0 = *(const float4*)&As[k][ty * 8];
            float4 af1 = *(const float4*)&As[k][ty * 8 + 4];
            float4 bf = *(const float4*)&Bs[k][tx * 4];
            float ar[8] = {af0.x, af0.y, af0.z, af0.w, af1.x, af1.y, af1.z, af1.w};
            float br[4] = {bf.x, bf.y, bf.z, bf.w};
#pragma unroll
            for (int i = 0; i < 8; i++)
#pragma unroll
                for (int j = 0; j < 4; j++)
                    acc[i][j] = fmaf(ar[i], br[j], acc[i][j]);
        }
    }

#pragma unroll
    for (int i = 0; i < 8; i++) {
        int row = m0 + ty * 8 + i;
        float* cp = Cout + (size_t)row * N + n0 + tx * 4;
        float4 o;
        o.x = acc[i][0]; o.y = acc[i][1]; o.z = acc[i][2]; o.w = acc[i][3];
        if (ACC) {
            float4 c = *(const float4*)cp;
            o.x += c.x; o.y += c.y; o.z += c.z; o.w += c.w;
        }
        *(float4*)cp = o;
    }
}

// ---------------------------------------------------------------------------
// Launch
// ---------------------------------------------------------------------------
extern "C" void kernel_launch(void* const* d_in, const int* in_sizes, int n_in,
                              void* d_out, int out_size) {
    const float* x      = (const float*)d_in[0];   // [B,T,C] = [2048, 1024]
    const float* rw     = (const float*)d_in[1];   // [16, 1024]
    const float* bias   = (const float*)d_in[2];   // [16]
    const float* gate_w = (const float*)d_in[3];   // [16, 1024, 256]
    const float* up_w   = (const float*)d_in[4];   // [16, 1024, 256]
    const float* down_w = (const float*)d_in[5];   // [16, 256, 1024] == [4096, 1024]
    const float* sgw    = (const float*)d_in[6];   // [2048, 1024]
    const float* suw    = (const float*)d_in[7];   // [2048, 1024]
    const float* sdw    = (const float*)d_in[8];   // [1024, 2048]
    float* out = (float*)d_out;                    // [2048, 1024]

    float *combine, *hw, *hs;
    cudaGetSymbolAddress((void**)&combine, g_combine);
    cudaGetSymbolAddress((void**)&hw, g_hw);
    cudaGetSymbolAddress((void**)&hs, g_hs);

    // 1. Router -> dense combine [S, E]
    router_kernel<<<S_TOK / 4, 128>>>(x, rw, bias, combine);

    // 2. Routed gate/up (all experts, combine-weighted): hw[S, E*H]
    dual_gemm_silu_kernel<false, true>
        <<<dim3((E_NUM * H_DIM) / 64, S_TOK / 128), 256>>>(
            x, gate_w, up_w, hw, combine, S_TOK, C_DIM, E_NUM * H_DIM, H_DIM);

    // 3. Shared expert gate/up: hs[S, HS]
    dual_gemm_silu_kernel<true, false>
        <<<dim3(HS_DIM / 64, S_TOK / 128), 256>>>(
            x, sgw, suw, hs, (const float*)nullptr, S_TOK, C_DIM, HS_DIM, 1);

    // 4. Routed down-projection: out = hw @ down_w   ([S,4096] @ [4096,1024])
    gemm_kernel<false, false>
        <<<dim3(C_DIM / 64, S_TOK / 128), 256>>>(
            hw, down_w, out, S_TOK, E_NUM * H_DIM, C_DIM);

    // 5. Shared down-projection (accumulate): out += hs @ sdw^T
    gemm_kernel<true, true>
        <<<dim3(C_DIM / 64, S_TOK / 128), 256>>>(
            hs, sdw, out, S_TOK, HS_DIM, C_DIM);
}

// round 2
// speedup vs baseline: 1.7514x; 1.7514x over previous
#include <cuda_runtime.h>
#include <math.h>

// Problem constants (match reference setup_inputs)
#define S_TOK 2048
#define C_DIM 1024
#define E_NUM 16
#define H_DIM 256
#define HS_DIM 2048
#define G_NUM 4
#define CAP   2048   // per-expert token capacity (worst case)

// Scratch (device globals: no allocation allowed)
__device__ int   g_counts[E_NUM];
__device__ int   g_elist[E_NUM * CAP];                     // expert -> token list
__device__ float g_wlist[E_NUM * CAP];                     // expert -> weight list
__device__ int   g_tok_e[S_TOK * 4];                       // token -> 4 experts
__device__ int   g_tok_pos[S_TOK * 4];                     // token -> pos in expert list
__device__ float g_hidden[(size_t)E_NUM * CAP * H_DIM];    // 32 MB weighted SwiGLU hidden
__device__ float g_dout[(size_t)E_NUM * CAP * C_DIM];      // 128 MB per-expert down output
__device__ float g_hs[(size_t)S_TOK * HS_DIM];             // 16 MB shared hidden

// ---------------------------------------------------------------------------
// Router: one warp per token. Grouped sigmoid top-k (group_limited_greedy).
// Emits gathered per-expert lists + token->(e,pos) map. Pos assignment order is
// nondeterministic (atomicAdd) but output values are invariant to it.
// ---------------------------------------------------------------------------
__global__ void router_kernel(const float* __restrict__ x,
                              const float* __restrict__ rw,
                              const float* __restrict__ bias,
                              int* __restrict__ counts,
                              int* __restrict__ elist,
                              float* __restrict__ wlist,
                              int* __restrict__ tok_e,
                              int* __restrict__ tok_pos) {
    int warp_id = (int)((blockIdx.x * blockDim.x + threadIdx.x) >> 5);
    int lane = threadIdx.x & 31;
    if (warp_id >= S_TOK) return;
    const float* xr = x + (size_t)warp_id * C_DIM;
    float logits[E_NUM];
#pragma unroll
    for (int e = 0; e < E_NUM; e++) {
        const float* wr = rw + (size_t)e * C_DIM;
        float p = 0.f;
        for (int c = lane; c < C_DIM; c += 32) p = fmaf(xr[c], wr[c], p);
#pragma unroll
        for (int off = 16; off; off >>= 1) p += __shfl_xor_sync(0xffffffffu, p, off);
        logits[e] = p;
    }
    if (lane == 0) {
        float sc[E_NUM], sb[E_NUM];
#pragma unroll
        for (int e = 0; e < E_NUM; e++) {
            sc[e] = 1.f / (1.f + expf(-logits[e]));
            sb[e] = sc[e] + bias[e];
        }
        // group scores = sum of top-2 biased scores per group of 4
        float gsc[G_NUM];
#pragma unroll
        for (int g = 0; g < G_NUM; g++) {
            float m1 = -1e30f, m2 = -1e30f;
#pragma unroll
            for (int j = 0; j < 4; j++) {
                float v = sb[g * 4 + j];
                if (v > m1) { m2 = m1; m1 = v; }
                else if (v > m2) { m2 = v; }
            }
            gsc[g] = m1 + m2;
        }
        int bg0 = 0;
        for (int g = 1; g < G_NUM; g++) if (gsc[g] > gsc[bg0]) bg0 = g;
        int bg1 = -1;
        for (int g = 0; g < G_NUM; g++) {
            if (g == bg0) continue;
            if (bg1 < 0 || gsc[g] > gsc[bg1]) bg1 = g;
        }
        bool allowed[E_NUM];
#pragma unroll
        for (int e = 0; e < E_NUM; e++) {
            int g = e >> 2;
            allowed[e] = (g == bg0) || (g == bg1);
        }
        int idx[4];
        for (int k = 0; k < 4; k++) {
            int bi = 0; float bv = -1e30f;
            for (int e = 0; e < E_NUM; e++)
                if (allowed[e] && sb[e] > bv) { bv = sb[e]; bi = e; }
            allowed[bi] = false;
            idx[k] = bi;
        }
        float wsum = 1e-20f;
        for (int k = 0; k < 4; k++) wsum += sc[idx[k]];
        for (int k = 0; k < 4; k++) {
            int e = idx[k];
            float w = sc[e] / wsum;
            int pos = atomicAdd(&counts[e], 1);
            elist[e * CAP + pos] = warp_id;
            wlist[e * CAP + pos] = w;
            tok_e[warp_id * 4 + k] = e;
            tok_pos[warp_id * 4 + k] = pos;
        }
    }
}

// ---------------------------------------------------------------------------
// Gathered routed dual GEMM + SiLU + combine weight:
//   hidden[e][pos][h] = silu(x[tok] @ gate_e)[h] * (x[tok] @ up_e)[h] * w
// grid: (H/64, CAP/128, E); block 256; BM=128 BN=64 BK=16; 8x4 microtile x2.
// ---------------------------------------------------------------------------
__global__ __launch_bounds__(256)
void routed_gateup_kernel(const float* __restrict__ x,
                          const float* __restrict__ gate_w,
                          const float* __restrict__ up_w,
                          float* __restrict__ hidden,
                          const int* __restrict__ counts,
                          const int* __restrict__ elist,
                          const float* __restrict__ wlist) {
    const int BM = 128, BN = 64, BK = 16;
    __shared__ float As[BK][BM + 4];
    __shared__ float Bgs[BK][BN + 4];
    __shared__ float Bus[BK][BN + 4];

    int e = blockIdx.z;
    int cnt = counts[e];
    int m0 = blockIdx.y * BM;
    if (m0 >= cnt) return;
    int n0 = blockIdx.x * BN;
    int tid = threadIdx.x;
    int tx = tid & 15;
    int ty = tid >> 4;

    const float* bg = gate_w + (size_t)e * C_DIM * H_DIM + n0;
    const float* bu = up_w + (size_t)e * C_DIM * H_DIM + n0;

    int arow = tid >> 2;
    int avec = tid & 3;
    int r0 = m0 + arow, r1 = m0 + arow + 64;
    int t0 = (r0 < cnt) ? elist[e * CAP + r0] : 0;
    int t1 = (r1 < cnt) ? elist[e * CAP + r1] : 0;
    int brow = tid >> 4;
    int bvec = tid & 15;

    float accg[8][4], accu[8][4];
#pragma unroll
    for (int i = 0; i < 8; i++)
#pragma unroll
        for (int j = 0; j < 4; j++) { accg[i][j] = 0.f; accu[i][j] = 0.f; }

    for (int k0 = 0; k0 < C_DIM; k0 += BK) {
        float4 a0 = *(const float4*)(x + (size_t)t0 * C_DIM + k0 + avec * 4);
        float4 a1 = *(const float4*)(x + (size_t)t1 * C_DIM + k0 + avec * 4);
        float4 bg0 = *(const float4*)(bg + (size_t)(k0 + brow) * H_DIM + bvec * 4);
        float4 bu0 = *(const float4*)(bu + (size_t)(k0 + brow) * H_DIM + bvec * 4);
        __syncthreads();
        As[avec * 4 + 0][arow] = a0.x;
        As[avec * 4 + 1][arow] = a0.y;
        As[avec * 4 + 2][arow] = a0.z;
        As[avec * 4 + 3][arow] = a0.w;
        As[avec * 4 + 0][arow + 64] = a1.x;
        As[avec * 4 + 1][arow + 64] = a1.y;
        As[avec * 4 + 2][arow + 64] = a1.z;
        As[avec * 4 + 3][arow + 64] = a1.w;
        *(float4*)&Bgs[brow][bvec * 4] = bg0;
        *(float4*)&Bus[brow][bvec * 4] = bu0;
        __syncthreads();
#pragma unroll
        for (int k = 0; k < BK; k++) {
            float4 af0 = *(const float4*)&As[k][ty * 8];
            float4 af1 = *(const float4*)&As[k][ty * 8 + 4];
            float4 bgf = *(const float4*)&Bgs[k][tx * 4];
            float4 buf = *(const float4*)&Bus[k][tx * 4];
            float ar[8] = {af0.x, af0.y, af0.z, af0.w, af1.x, af1.y, af1.z, af1.w};
            float gr[4] = {bgf.x, bgf.y, bgf.z, bgf.w};
            float ur[4] = {buf.x, buf.y, buf.z, buf.w};
#pragma unroll
            for (int i = 0; i < 8; i++) {
#pragma unroll
                for (int j = 0; j < 4; j++) {
                    accg[i][j] = fmaf(ar[i], gr[j], accg[i][j]);
                    accu[i][j] = fmaf(ar[i], ur[j], accu[i][j]);
                }
            }
        }
    }

#pragma unroll
    for (int i = 0; i < 8; i++) {
        int row = m0 + ty * 8 + i;
        if (row >= cnt) continue;
        float scale = wlist[e * CAP + row];
        float4 o;
        float g, u;
        g = accg[i][0]; u = accu[i][0]; o.x = (g / (1.f + expf(-g))) * u * scale;
        g = accg[i][1]; u = accu[i][1]; o.y = (g / (1.f + expf(-g))) * u * scale;
        g = accg[i][2]; u = accu[i][2]; o.z = (g / (1.f + expf(-g))) * u * scale;
        g = accg[i][3]; u = accu[i][3]; o.w = (g / (1.f + expf(-g))) * u * scale;
        *(float4*)(hidden + ((size_t)e * CAP + row) * H_DIM + n0 + tx * 4) = o;
    }
}

// ---------------------------------------------------------------------------
// Routed down-proj per expert: dout[e][pos][:] = hidden[e][pos][:] @ down_w[e]
// grid: (C/64, CAP/128, E). K = H_DIM = 256.
// ---------------------------------------------------------------------------
__global__ __launch_bounds__(256)
void routed_down_kernel(const float* __restrict__ hidden,
                        const float* __restrict__ down_w,
                        float* __restrict__ dout,
                        const int* __restrict__ counts) {
    const int BM = 128, BN = 64, BK = 16;
    __shared__ float As[BK][BM + 4];
    __shared__ float Bs[BK][BN + 4];

    int e = blockIdx.z;
    int cnt = counts[e];
    int m0 = blockIdx.y * BM;
    if (m0 >= cnt) return;
    int n0 = blockIdx.x * BN;
    int tid = threadIdx.x;
    int tx = tid & 15;
    int ty = tid >> 4;

    const float* A = hidden + (size_t)e * CAP * H_DIM;
    const float* B = down_w + (size_t)e * H_DIM * C_DIM;
    float* C = dout + (size_t)e * CAP * C_DIM;

    float acc[8][4];
#pragma unroll
    for (int i = 0; i < 8; i++)
#pragma unroll
        for (int j = 0; j < 4; j++) acc[i][j] = 0.f;

    int arow = tid >> 2;
    int avec = tid & 3;
    int brow = tid >> 4;
    int bvec = tid & 15;

    for (int k0 = 0; k0 < H_DIM; k0 += BK) {
        float4 a0 = *(const float4*)(A + (size_t)(m0 + arow) * H_DIM + k0 + avec * 4);
        float4 a1 = *(const float4*)(A + (size_t)(m0 + arow + 64) * H_DIM + k0 + avec * 4);
        float4 b0 = *(const float4*)(B + (size_t)(k0 + brow) * C_DIM + n0 + bvec * 4);
        __syncthreads();
        As[avec * 4 + 0][arow] = a0.x;
        As[avec * 4 + 1][arow] = a0.y;
        As[avec * 4 + 2][arow] = a0.z;
        As[avec * 4 + 3][arow] = a0.w;
        As[avec * 4 + 0][arow + 64] = a1.x;
        As[avec * 4 + 1][arow + 64] = a1.y;
        As[avec * 4 + 2][arow + 64] = a1.z;
        As[avec * 4 + 3][arow + 64] = a1.w;
        *(float4*)&Bs[brow][bvec * 4] = b0;
        __syncthreads();
#pragma unroll
        for (int k = 0; k < BK; k++) {
            float4 af0 = *(const float4*)&As[k][ty * 8];
            float4 af1 = *(const float4*)&As[k][ty * 8 + 4];
            float4 bf = *(const float4*)&Bs[k][tx * 4];
            float ar[8] = {af0.x, af0.y, af0.z, af0.w, af1.x, af1.y, af1.z, af1.w};
            float br[4] = {bf.x, bf.y, bf.z, bf.w};
#pragma unroll
            for (int i = 0; i < 8; i++)
#pragma unroll
                for (int j = 0; j < 4; j++)
                    acc[i][j] = fmaf(ar[i], br[j], acc[i][j]);
        }
    }

#pragma unroll
    for (int i = 0; i < 8; i++) {
        int row = m0 + ty * 8 + i;
        if (row >= cnt) continue;
        float4 o;
        o.x = acc[i][0]; o.y = acc[i][1]; o.z = acc[i][2]; o.w = acc[i][3];
        *(float4*)(C + (size_t)row * C_DIM + n0 + tx * 4) = o;
    }
}

// ---------------------------------------------------------------------------
// Shared-expert dual GEMM + SiLU (B transposed [N, K] row-major)
// ---------------------------------------------------------------------------
__global__ __launch_bounds__(256)
void shared_gateup_kernel(const float* __restrict__ A,
                          const float* __restrict__ Bg,
                          const float* __restrict__ Bu,
                          float* __restrict__ Cout) {
    const int BM = 128, BN = 64, BK = 16;
    __shared__ float As[BK][BM + 4];
    __shared__ float Bgs[BK][BN + 4];
    __shared__ float Bus[BK][BN + 4];

    int n0 = blockIdx.x * BN;
    int m0 = blockIdx.y * BM;
    int tid = threadIdx.x;
    int tx = tid & 15;
    int ty = tid >> 4;

    const float* bg = Bg + (size_t)n0 * C_DIM;
    const float* bu = Bu + (size_t)n0 * C_DIM;

    float accg[8][4], accu[8][4];
#pragma unroll
    for (int i = 0; i < 8; i++)
#pragma unroll
        for (int j = 0; j < 4; j++) { accg[i][j] = 0.f; accu[i][j] = 0.f; }

    int arow = tid >> 2;
    int avec = tid & 3;

    for (int k0 = 0; k0 < C_DIM; k0 += BK) {
        float4 a0 = *(const float4*)(A + (size_t)(m0 + arow) * C_DIM + k0 + avec * 4);
        float4 a1 = *(const float4*)(A + (size_t)(m0 + arow + 64) * C_DIM + k0 + avec * 4);
        float4 bg0 = *(const float4*)(bg + (size_t)arow * C_DIM + k0 + avec * 4);
        float4 bu0 = *(const float4*)(bu + (size_t)arow * C_DIM + k0 + avec * 4);
        __syncthreads();
        As[avec * 4 + 0][arow] = a0.x;
        As[avec * 4 + 1][arow] = a0.y;
        As[avec * 4 + 2][arow] = a0.z;
        As[avec * 4 + 3][arow] = a0.w;
        As[avec * 4 + 0][arow + 64] = a1.x;
        As[avec * 4 + 1][arow + 64] = a1.y;
        As[avec * 4 + 2][arow + 64] = a1.z;
        As[avec * 4 + 3][arow + 64] = a1.w;
        Bgs[avec * 4 + 0][arow] = bg0.x;
        Bgs[avec * 4 + 1][arow] = bg0.y;
        Bgs[avec * 4 + 2][arow] = bg0.z;
        Bgs[avec * 4 + 3][arow] = bg0.w;
        Bus[avec * 4 + 0][arow] = bu0.x;
        Bus[avec * 4 + 1][arow] = bu0.y;
        Bus[avec * 4 + 2][arow] = bu0.z;
        Bus[avec * 4 + 3][arow] = bu0.w;
        __syncthreads();
#pragma unroll
        for (int k = 0; k < BK; k++) {
            float4 af0 = *(const float4*)&As[k][ty * 8];
            float4 af1 = *(const float4*)&As[k][ty * 8 + 4];
            float4 bgf = *(const float4*)&Bgs[k][tx * 4];
            float4 buf = *(const float4*)&Bus[k][tx * 4];
            float ar[8] = {af0.x, af0.y, af0.z, af0.w, af1.x, af1.y, af1.z, af1.w};
            float gr[4] = {bgf.x, bgf.y, bgf.z, bgf.w};
            float ur[4] = {buf.x, buf.y, buf.z, buf.w};
#pragma unroll
            for (int i = 0; i < 8; i++) {
#pragma unroll
                for (int j = 0; j < 4; j++) {
                    accg[i][j] = fmaf(ar[i], gr[j], accg[i][j]);
                    accu[i][j] = fmaf(ar[i], ur[j], accu[i][j]);
                }
            }
        }
    }

#pragma unroll
    for (int i = 0; i < 8; i++) {
        int row = m0 + ty * 8 + i;
        float4 o;
        float g, u;
        g = accg[i][0]; u = accu[i][0]; o.x = (g / (1.f + expf(-g))) * u;
        g = accg[i][1]; u = accu[i][1]; o.y = (g / (1.f + expf(-g))) * u;
        g = accg[i][2]; u = accu[i][2]; o.z = (g / (1.f + expf(-g))) * u;
        g = accg[i][3]; u = accu[i][3]; o.w = (g / (1.f + expf(-g))) * u;
        *(float4*)(Cout + (size_t)row * HS_DIM + n0 + tx * 4) = o;
    }
}

// ---------------------------------------------------------------------------
// Shared down: out = hs @ sdw^T  (B is [C, HS] row-major -> transposed access)
// ---------------------------------------------------------------------------
__global__ __launch_bounds__(256)
void shared_down_kernel(const float* __restrict__ A,
                        const float* __restrict__ B,
                        float* __restrict__ Cout) {
    const int BM = 128, BN = 64, BK = 16;
    __shared__ float As[BK][BM + 4];
    __shared__ float Bs[BK][BN + 4];

    int n0 = blockIdx.x * BN;
    int m0 = blockIdx.y * BM;
    int tid = threadIdx.x;
    int tx = tid & 15;
    int ty = tid >> 4;

    float acc[8][4];
#pragma unroll
    for (int i = 0; i < 8; i++)
#pragma unroll
        for (int j = 0; j < 4; j++) acc[i][j] = 0.f;

    int arow = tid >> 2;
    int avec = tid & 3;

    for (int k0 = 0; k0 < HS_DIM; k0 += BK) {
        float4 a0 = *(const float4*)(A + (size_t)(m0 + arow) * HS_DIM + k0 + avec * 4);
        float4 a1 = *(const float4*)(A + (size_t)(m0 + arow + 64) * HS_DIM + k0 + avec * 4);
        float4 b0 = *(const float4*)(B + (size_t)(n0 + arow) * HS_DIM + k0 + avec * 4);
        __syncthreads();
        As[avec * 4 + 0][arow] = a0.x;
        As[avec * 4 + 1][arow] = a0.y;
        As[avec * 4 + 2][arow] = a0.z;
        As[avec * 4 + 3][arow] = a0.w;
        As[avec * 4 + 0][arow + 64] = a1.x;
        As[avec * 4 + 1][arow + 64] = a1.y;
        As[avec * 4 + 2][arow + 64] = a1.z;
        As[avec * 4 + 3][arow + 64] = a1.w;
        Bs[avec * 4 + 0][arow] = b0.x;
        Bs[avec * 4 + 1][arow] = b0.y;
        Bs[avec * 4 + 2][arow] = b0.z;
        Bs[avec * 4 + 3][arow] = b0.w;
        __syncthreads();
#pragma unroll
        for (int k = 0; k < BK; k++) {
            float4 af0 = *(const float4*)&As[k][ty * 8];
            float4 af1 = *(const float4*)&As[k][ty * 8 + 4];
            float4 bf = *(const float4*)&Bs[k][tx * 4];
            float ar[8] = {af0.x, af0.y, af0.z, af0.w, af1.x, af1.y, af1.z, af1.w};
            float br[4] = {bf.x, bf.y, bf.z, bf.w};
#pragma unroll
            for (int i = 0; i < 8; i++)
#pragma unroll
                for (int j = 0; j < 4; j++)
                    acc[i][j] = fmaf(ar[i], br[j], acc[i][j]);
        }
    }

#pragma unroll
    for (int i = 0; i < 8; i++) {
        int row = m0 + ty * 8 + i;
        float4 o;
        o.x = acc[i][0]; o.y = acc[i][1]; o.z = acc[i][2]; o.w = acc[i][3];
        *(float4*)(Cout + (size_t)row * C_DIM + n0 + tx * 4) = o;
    }
}

// ---------------------------------------------------------------------------
// Final combine: out[s] += sum_k dout[e_k][pos_k]   (out holds shared result)
// grid: S_TOK blocks x 256 threads, one float4 per thread.
// ---------------------------------------------------------------------------
__global__ void combine_kernel(const int* __restrict__ tok_e,
                               const int* __restrict__ tok_pos,
                               const float* __restrict__ dout,
                               float* __restrict__ out) {
    int s = blockIdx.x;
    int c = threadIdx.x * 4;
    float4 acc = *(const float4*)(out + (size_t)s * C_DIM + c);
#pragma unroll
    for (int k = 0; k < 4; k++) {
        int e = tok_e[s * 4 + k];
        int p = tok_pos[s * 4 + k];
        float4 v = *(const float4*)(dout + ((size_t)e * CAP + p) * C_DIM + c);
        acc.x += v.x; acc.y += v.y; acc.z += v.z; acc.w += v.w;
    }
    *(float4*)(out + (size_t)s * C_DIM + c) = acc;
}

// ---------------------------------------------------------------------------
// Launch
// ---------------------------------------------------------------------------
extern "C" void kernel_launch(void* const* d_in, const int* in_sizes, int n_in,
                              void* d_out, int out_size) {
    const float* x      = (const float*)d_in[0];   // [2048, 1024]
    const float* rw     = (const float*)d_in[1];   // [16, 1024]
    const float* bias   = (const float*)d_in[2];   // [16]
    const float* gate_w = (const float*)d_in[3];   // [16, 1024, 256]
    const float* up_w   = (const float*)d_in[4];   // [16, 1024, 256]
    const float* down_w = (const float*)d_in[5];   // [16, 256, 1024]
    const float* sgw    = (const float*)d_in[6];   // [2048, 1024]
    const float* suw    = (const float*)d_in[7];   // [2048, 1024]
    const float* sdw    = (const float*)d_in[8];   // [1024, 2048]
    float* out = (float*)d_out;                    // [2048, 1024]

    int *counts, *elist, *tok_e, *tok_pos;
    float *wlist, *hidden, *dout, *hs;
    cudaGetSymbolAddress((void**)&counts, g_counts);
    cudaGetSymbolAddress((void**)&elist, g_elist);
    cudaGetSymbolAddress((void**)&wlist, g_wlist);
    cudaGetSymbolAddress((void**)&tok_e, g_tok_e);
    cudaGetSymbolAddress((void**)&tok_pos, g_tok_pos);
    cudaGetSymbolAddress((void**)&hidden, g_hidden);
    cudaGetSymbolAddress((void**)&dout, g_dout);
    cudaGetSymbolAddress((void**)&hs, g_hs);

    // 0. zero per-expert counts
    cudaMemsetAsync(counts, 0, E_NUM * sizeof(int));

    // 1. Router -> gathered per-expert token lists
    router_kernel<<<S_TOK / 4, 128>>>(x, rw, bias, counts, elist, wlist,
                                      tok_e, tok_pos);

    // 2. Routed gate/up over gathered tokens only (~512/expert)
    routed_gateup_kernel<<<dim3(H_DIM / 64, CAP / 128, E_NUM), 256>>>(
        x, gate_w, up_w, hidden, counts, elist, wlist);

    // 3. Routed down-projection per expert
    routed_down_kernel<<<dim3(C_DIM / 64, CAP / 128, E_NUM), 256>>>(
        hidden, down_w, dout, counts);

    // 4. Shared expert gate/up: hs[S, HS]
    shared_gateup_kernel<<<dim3(HS_DIM / 64, S_TOK / 128), 256>>>(
        x, sgw, suw, hs);

    // 5. Shared down-projection (writes out)
    shared_down_kernel<<<dim3(C_DIM / 64, S_TOK / 128), 256>>>(hs, sdw, out);

    // 6. Combine: out += routed expert rows
    combine_kernel<<<S_TOK, 256>>>(tok_e, tok_pos, dout, out);
}

// round 4
// speedup vs baseline: 3.2336x; 1.8463x over previous
#include <cuda_runtime.h>
#include <math.h>
#include <stdint.h>

// Problem constants
#define S_TOK 2048
#define C_DIM 1024
#define E_NUM 16
#define H_DIM 256
#define HS_DIM 2048
#define CAP   2048

#define BKP 20   // padded K stride (floats) for smem tiles, conflict-free

// ---------------------------------------------------------------------------
// Device scratch (no allocation allowed)
// ---------------------------------------------------------------------------
__device__ int   g_counts[E_NUM];
__device__ int   g_elist[E_NUM * CAP];
__device__ float g_wlist[E_NUM * CAP];
__device__ int   g_tok_e[S_TOK * 4];
__device__ int   g_tok_pos[S_TOK * 4];
__device__ float g_hidden[(size_t)E_NUM * CAP * H_DIM];
__device__ float g_dout[(size_t)E_NUM * CAP * C_DIM];
__device__ float g_hs[(size_t)S_TOK * HS_DIM];
__device__ float g_gate_t[(size_t)E_NUM * H_DIM * C_DIM];   // [e][H][C] K-major
__device__ float g_up_t[(size_t)E_NUM * H_DIM * C_DIM];
__device__ float g_down_t[(size_t)E_NUM * C_DIM * H_DIM];   // [e][C][H] K-major

// ---------------------------------------------------------------------------
// Helpers
// ---------------------------------------------------------------------------
__device__ __forceinline__ uint32_t smem_u32(const void* p) {
    uint32_t a;
    asm("{ .reg .u64 t; cvta.to.shared.u64 t, %1; cvt.u32.u64 %0, t; }" : "=r"(a) : "l"(p));
    return a;
}
__device__ __forceinline__ uint32_t f2tf32(float f) {
    uint32_t r;
    asm("cvt.rna.tf32.f32 %0, %1;" : "=r"(r) : "f"(f));
    return r;
}
__device__ __forceinline__ void sts128(uint32_t a, uint32_t x, uint32_t y, uint32_t z, uint32_t w) {
    asm volatile("st.shared.v4.b32 [%0], {%1,%2,%3,%4};" :: "r"(a), "r"(x), "r"(y), "r"(z), "r"(w));
}
__device__ __forceinline__ void mma8(float* d, const uint32_t* a, const uint32_t* b) {
    asm volatile(
        "mma.sync.aligned.m16n8k8.row.col.f32.tf32.tf32.f32 "
        "{%0,%1,%2,%3}, {%4,%5,%6,%7}, {%8,%9}, {%0,%1,%2,%3};"
        : "+f"(d[0]), "+f"(d[1]), "+f"(d[2]), "+f"(d[3])
        : "r"(a[0]), "r"(a[1]), "r"(a[2]), "r"(a[3]), "r"(b[0]), "r"(b[1]));
}
// A fragment: 16x8 tile at row base 'row' (already includes grp), kstep ks
__device__ __forceinline__ void ld_afrag(uint32_t* a, const uint32_t* As, int row, int ks, int thr) {
    const uint32_t* p = As + row * BKP + ks + thr;
    a[0] = p[0];
    a[1] = p[8 * BKP];
    a[2] = p[4];
    a[3] = p[8 * BKP + 4];
}
__device__ __forceinline__ void ld_bfrag(uint32_t* b, const uint32_t* Bs, int n, int ks, int thr) {
    const uint32_t* p = Bs + n * BKP + ks + thr;
    b[0] = p[0];
    b[1] = p[4];
}

// ---------------------------------------------------------------------------
// Router: warp per token, grouped sigmoid top-k, gathered per-expert lists
// ---------------------------------------------------------------------------
__global__ void router_kernel(const float* __restrict__ x,
                              const float* __restrict__ rw,
                              const float* __restrict__ bias,
                              int* __restrict__ counts, int* __restrict__ elist,
                              float* __restrict__ wlist, int* __restrict__ tok_e,
                              int* __restrict__ tok_pos) {
    int warp_id = (int)((blockIdx.x * blockDim.x + threadIdx.x) >> 5);
    int lane = threadIdx.x & 31;
    if (warp_id >= S_TOK) return;
    const float* xr = x + (size_t)warp_id * C_DIM;
    float logits[E_NUM];
#pragma unroll
    for (int e = 0; e < E_NUM; e++) {
        const float* wr = rw + (size_t)e * C_DIM;
        float p = 0.f;
        for (int c = lane; c < C_DIM; c += 32) p = fmaf(xr[c], wr[c], p);
#pragma unroll
        for (int off = 16; off; off >>= 1) p += __shfl_xor_sync(0xffffffffu, p, off);
        logits[e] = p;
    }
    if (lane == 0) {
        float sc[E_NUM], sb[E_NUM];
#pragma unroll
        for (int e = 0; e < E_NUM; e++) {
            sc[e] = 1.f / (1.f + expf(-logits[e]));
            sb[e] = sc[e] + bias[e];
        }
        float gsc[4];
#pragma unroll
        for (int g = 0; g < 4; g++) {
            float m1 = -1e30f, m2 = -1e30f;
#pragma unroll
            for (int j = 0; j < 4; j++) {
                float v = sb[g * 4 + j];
                if (v > m1) { m2 = m1; m1 = v; } else if (v > m2) m2 = v;
            }
            gsc[g] = m1 + m2;
        }
        int bg0 = 0;
        for (int g = 1; g < 4; g++) if (gsc[g] > gsc[bg0]) bg0 = g;
        int bg1 = -1;
        for (int g = 0; g < 4; g++) {
            if (g == bg0) continue;
            if (bg1 < 0 || gsc[g] > gsc[bg1]) bg1 = g;
        }
        bool allowed[E_NUM];
#pragma unroll
        for (int e = 0; e < E_NUM; e++) {
            int g = e >> 2;
            allowed[e] = (g == bg0) || (g == bg1);
        }
        int idx[4];
        for (int k = 0; k < 4; k++) {
            int bi = 0; float bv = -1e30f;
            for (int e = 0; e < E_NUM; e++)
                if (allowed[e] && sb[e] > bv) { bv = sb[e]; bi = e; }
            allowed[bi] = false;
            idx[k] = bi;
        }
        float wsum = 1e-20f;
        for (int k = 0; k < 4; k++) wsum += sc[idx[k]];
        for (int k = 0; k < 4; k++) {
            int e = idx[k];
            int pos = atomicAdd(&counts[e], 1);
            elist[e * CAP + pos] = warp_id;
            wlist[e * CAP + pos] = sc[e] / wsum;
            tok_e[warp_id * 4 + k] = e;
            tok_pos[warp_id * 4 + k] = pos;
        }
    }
}

// ---------------------------------------------------------------------------
// Per-expert matrix transpose: in [z][R][C] -> out [z][C][R]
// ---------------------------------------------------------------------------
__global__ void transpose_kernel(const float* __restrict__ in, float* __restrict__ out,
                                 int R, int C) {
    __shared__ float t[32][33];
    int z = blockIdx.z;
    in += (size_t)z * R * C;
    out += (size_t)z * R * C;
    int c0 = blockIdx.x * 32, r0 = blockIdx.y * 32;
    int tx = threadIdx.x, ty = threadIdx.y;
#pragma unroll
    for (int j = 0; j < 32; j += 8)
        t[ty + j][tx] = in[(size_t)(r0 + ty + j) * C + c0 + tx];
    __syncthreads();
#pragma unroll
    for (int j = 0; j < 32; j += 8)
        out[(size_t)(c0 + ty + j) * R + r0 + tx] = t[tx][ty + j];
}

// ---------------------------------------------------------------------------
// tf32 mma.sync dual GEMM + SiLU epilogue (gate/up).
// A [M, C] (rows gathered if ROUTED), Bg/Bu K-major [N, C].
// Tile 128x128, BK=16, 512 threads (4x4 warps, warp tile 32x32 per GEMM).
// ---------------------------------------------------------------------------
template <bool ROUTED>
__global__ __launch_bounds__(512)
void mma_gateup(const float* __restrict__ X, const float* __restrict__ Bgm,
                const float* __restrict__ Bum, float* __restrict__ Cc,
                const int* __restrict__ counts, const int* __restrict__ elist,
                const float* __restrict__ wlist) {
    const int Kd = C_DIM;
    int e = 0, cnt = 0;
    int m0 = blockIdx.y * 128, n0 = blockIdx.x * 128;
    if (ROUTED) {
        e = blockIdx.z;
        cnt = counts[e];
        if (m0 >= cnt) return;
        Bgm += (size_t)e * H_DIM * C_DIM;
        Bum += (size_t)e * H_DIM * C_DIM;
    }

    __shared__ float As[128 * BKP];
    __shared__ float Bgs[128 * BKP];
    __shared__ float Bus[128 * BKP];

    int tid = threadIdx.x, wid = tid >> 5, lane = tid & 31;
    int grp = lane >> 2, thr = lane & 3;
    int wm = (wid & 3) * 32, wn = (wid >> 2) * 32;

    // loader mapping: 512 threads, one float4 per array per chunk
    int lrow = tid >> 2, lvec = tid & 3;
    int atok;
    if (ROUTED) {
        int idx = m0 + lrow;
        atok = elist[e * CAP + (idx < cnt ? idx : 0)];
    } else {
        atok = m0 + lrow;
    }
    const float* aptr = X + (size_t)atok * Kd + lvec * 4;
    const float* gptr = Bgm + (size_t)(n0 + lrow) * Kd + lvec * 4;
    const float* uptr = Bum + (size_t)(n0 + lrow) * Kd + lvec * 4;
    uint32_t soff = (uint32_t)(lrow * BKP + lvec * 4) * 4;
    uint32_t asb = smem_u32(As) + soff;
    uint32_t gsb = smem_u32(Bgs) + soff;
    uint32_t usb = smem_u32(Bus) + soff;

    float accg[2][4][4], accu[2][4][4];
#pragma unroll
    for (int i = 0; i < 2; i++)
#pragma unroll
        for (int j = 0; j < 4; j++)
#pragma unroll
            for (int v = 0; v < 4; v++) { accg[i][j][v] = 0.f; accu[i][j][v] = 0.f; }

    float4 ra = *(const float4*)aptr;
    float4 rg = *(const float4*)gptr;
    float4 ru = *(const float4*)uptr;

    const int NCH = Kd / 16;
    const uint32_t* Au = (const uint32_t*)As;
    const uint32_t* Gu = (const uint32_t*)Bgs;
    const uint32_t* Uu = (const uint32_t*)Bus;

    for (int i = 0; i < NCH; i++) {
        __syncthreads();
        sts128(asb, f2tf32(ra.x), f2tf32(ra.y), f2tf32(ra.z), f2tf32(ra.w));
        sts128(gsb, f2tf32(rg.x), f2tf32(rg.y), f2tf32(rg.z), f2tf32(rg.w));
        sts128(usb, f2tf32(ru.x), f2tf32(ru.y), f2tf32(ru.z), f2tf32(ru.w));
        __syncthreads();
        if (i + 1 < NCH) {
            int k0 = (i + 1) * 16;
            ra = *(const float4*)(aptr + k0);
            rg = *(const float4*)(gptr + k0);
            ru = *(const float4*)(uptr + k0);
        }
#pragma unroll
        for (int ks = 0; ks < 16; ks += 8) {
            uint32_t af[2][4];
            ld_afrag(af[0], Au, wm + grp, ks, thr);
            ld_afrag(af[1], Au, wm + 16 + grp, ks, thr);
            uint32_t bg[4][2], bu[4][2];
#pragma unroll
            for (int j = 0; j < 4; j++) {
                ld_bfrag(bg[j], Gu, wn + j * 8 + grp, ks, thr);
                ld_bfrag(bu[j], Uu, wn + j * 8 + grp, ks, thr);
            }
#pragma unroll
            for (int mi = 0; mi < 2; mi++)
#pragma unroll
                for (int j = 0; j < 4; j++) {
                    mma8(accg[mi][j], af[mi], bg[j]);
                    mma8(accu[mi][j], af[mi], bu[j]);
                }
        }
    }

    // epilogue: silu(g)*u*scale
#pragma unroll
    for (int mi = 0; mi < 2; mi++) {
#pragma unroll
        for (int half = 0; half < 2; half++) {
            int lrowl = wm + mi * 16 + grp + half * 8;
            int gidx = m0 + lrowl;
            float scale = 1.f;
            float* orow;
            bool valid = true;
            if (ROUTED) {
                valid = gidx < cnt;
                if (valid) {
                    scale = wlist[e * CAP + gidx];
                    orow = g_hidden + ((size_t)e * CAP + gidx) * H_DIM + n0;
                } else orow = nullptr;
            } else {
                orow = Cc + (size_t)gidx * HS_DIM + n0;
            }
            if (valid) {
#pragma unroll
                for (int j = 0; j < 4; j++) {
                    int c = wn + j * 8 + thr * 2;
                    float g0 = accg[mi][j][half * 2], g1 = accg[mi][j][half * 2 + 1];
                    float u0 = accu[mi][j][half * 2], u1 = accu[mi][j][half * 2 + 1];
                    float2 o;
                    o.x = (g0 / (1.f + expf(-g0))) * u0 * scale;
                    o.y = (g1 / (1.f + expf(-g1))) * u1 * scale;
                    *(float2*)(orow + c) = o;
                }
            }
        }
    }
}

// ---------------------------------------------------------------------------
// tf32 mma.sync single GEMM (down projections). B K-major [N, Kd].
// ---------------------------------------------------------------------------
template <bool ROUTED>
__global__ __launch_bounds__(512)
void mma_down(const float* __restrict__ A, const float* __restrict__ B,
              float* __restrict__ Cc, int Kd, const int* __restrict__ counts) {
    int e = 0, cnt = 0;
    int m0 = blockIdx.y * 128, n0 = blockIdx.x * 128;
    if (ROUTED) {
        e = blockIdx.z;
        cnt = counts[e];
        if (m0 >= cnt) return;
        A += (size_t)e * CAP * H_DIM;
        B += (size_t)e * C_DIM * H_DIM;
        Cc += (size_t)e * CAP * C_DIM;
    }

    __shared__ float As[128 * BKP];
    __shared__ float Bs[128 * BKP];

    int tid = threadIdx.x, wid = tid >> 5, lane = tid & 31;
    int grp = lane >> 2, thr = lane & 3;
    int wm = (wid & 3) * 32, wn = (wid >> 2) * 32;

    int lrow = tid >> 2, lvec = tid & 3;
    const float* aptr = A + (size_t)(m0 + lrow) * Kd + lvec * 4;
    const float* bptr = B + (size_t)(n0 + lrow) * Kd + lvec * 4;
    uint32_t soff = (uint32_t)(lrow * BKP + lvec * 4) * 4;
    uint32_t asb = smem_u32(As) + soff;
    uint32_t bsb = smem_u32(Bs) + soff;

    float acc[2][4][4];
#pragma unroll
    for (int i = 0; i < 2; i++)
#pragma unroll
        for (int j = 0; j < 4; j++)
#pragma unroll
            for (int v = 0; v < 4; v++) acc[i][j][v] = 0.f;

    float4 ra = *(const float4*)aptr;
    float4 rb = *(const float4*)bptr;

    const int NCH = Kd / 16;
    const uint32_t* Au = (const uint32_t*)As;
    const uint32_t* Bu = (const uint32_t*)Bs;

    for (int i = 0; i < NCH; i++) {
        __syncthreads();
        sts128(asb, f2tf32(ra.x), f2tf32(ra.y), f2tf32(ra.z), f2tf32(ra.w));
        sts128(bsb, f2tf32(rb.x), f2tf32(rb.y), f2tf32(rb.z), f2tf32(rb.w));
        __syncthreads();
        if (i + 1 < NCH) {
            int k0 = (i + 1) * 16;
            ra = *(const float4*)(aptr + k0);
            rb = *(const float4*)(bptr + k0);
        }
#pragma unroll
        for (int ks = 0; ks < 16; ks += 8) {
            uint32_t af[2][4];
            ld_afrag(af[0], Au, wm + grp, ks, thr);
            ld_afrag(af[1], Au, wm + 16 + grp, ks, thr);
            uint32_t bf[4][2];
#pragma unroll
            for (int j = 0; j < 4; j++)
                ld_bfrag(bf[j], Bu, wn + j * 8 + grp, ks, thr);
#pragma unroll
            for (int mi = 0; mi < 2; mi++)
#pragma unroll
                for (int j = 0; j < 4; j++)
                    mma8(acc[mi][j], af[mi], bf[j]);
        }
    }

#pragma unroll
    for (int mi = 0; mi < 2; mi++) {
#pragma unroll
        for (int half = 0; half < 2; half++) {
            int lrowl = wm + mi * 16 + grp + half * 8;
            int gidx = m0 + lrowl;
            bool valid = ROUTED ? (gidx < cnt) : true;
            if (valid) {
                float* orow = Cc + (size_t)gidx * C_DIM + n0;
#pragma unroll
                for (int j = 0; j < 4; j++) {
                    int c = wn + j * 8 + thr * 2;
                    float2 o;
                    o.x = acc[mi][j][half * 2];
                    o.y = acc[mi][j][half * 2 + 1];
                    *(float2*)(orow + c) = o;
                }
            }
        }
    }
}

// ---------------------------------------------------------------------------
// Final combine: out[s] += sum_k dout[e_k][pos_k]
// ---------------------------------------------------------------------------
__global__ void combine_kernel(const int* __restrict__ tok_e,
                               const int* __restrict__ tok_pos,
                               const float* __restrict__ dout,
                               float* __restrict__ out) {
    int s = blockIdx.x;
    int c = threadIdx.x * 4;
    float4 acc = *(const float4*)(out + (size_t)s * C_DIM + c);
#pragma unroll
    for (int k = 0; k < 4; k++) {
        int e = tok_e[s * 4 + k];
        int p = tok_pos[s * 4 + k];
        float4 v = *(const float4*)(dout + ((size_t)e * CAP + p) * C_DIM + c);
        acc.x += v.x; acc.y += v.y; acc.z += v.z; acc.w += v.w;
    }
    *(float4*)(out + (size_t)s * C_DIM + c) = acc;
}

// ---------------------------------------------------------------------------
// Launch
// ---------------------------------------------------------------------------
extern "C" void kernel_launch(void* const* d_in, const int* in_sizes, int n_in,
                              void* d_out, int out_size) {
    const float* x      = (const float*)d_in[0];
    const float* rw     = (const float*)d_in[1];
    const float* bias   = (const float*)d_in[2];
    const float* gate_w = (const float*)d_in[3];
    const float* up_w   = (const float*)d_in[4];
    const float* down_w = (const float*)d_in[5];
    const float* sgw    = (const float*)d_in[6];
    const float* suw    = (const float*)d_in[7];
    const float* sdw    = (const float*)d_in[8];
    float* out = (float*)d_out;

    int *counts, *elist, *tok_e, *tok_pos;
    float *wlist, *hidden, *dout, *hs, *gate_t, *up_t, *down_t;
    cudaGetSymbolAddress((void**)&counts, g_counts);
    cudaGetSymbolAddress((void**)&elist, g_elist);
    cudaGetSymbolAddress((void**)&wlist, g_wlist);
    cudaGetSymbolAddress((void**)&tok_e, g_tok_e);
    cudaGetSymbolAddress((void**)&tok_pos, g_tok_pos);
    cudaGetSymbolAddress((void**)&hidden, g_hidden);
    cudaGetSymbolAddress((void**)&dout, g_dout);
    cudaGetSymbolAddress((void**)&hs, g_hs);
    cudaGetSymbolAddress((void**)&gate_t, g_gate_t);
    cudaGetSymbolAddress((void**)&up_t, g_up_t);
    cudaGetSymbolAddress((void**)&down_t, g_down_t);

    cudaMemsetAsync(counts, 0, E_NUM * sizeof(int));

    // Router + K-major weight transposes (independent of each other)
    router_kernel<<<S_TOK / 4, 128>>>(x, rw, bias, counts, elist, wlist, tok_e, tok_pos);
    transpose_kernel<<<dim3(H_DIM / 32, C_DIM / 32, E_NUM), dim3(32, 8)>>>(gate_w, gate_t, C_DIM, H_DIM);
    transpose_kernel<<<dim3(H_DIM / 32, C_DIM / 32, E_NUM), dim3(32, 8)>>>(up_w, up_t, C_DIM, H_DIM);
    transpose_kernel<<<dim3(C_DIM / 32, H_DIM / 32, E_NUM), dim3(32, 8)>>>(down_w, down_t, H_DIM, C_DIM);

    // Routed gate/up -> hidden (gathered, combine-weighted)
    mma_gateup<true><<<dim3(H_DIM / 128, CAP / 128, E_NUM), 512>>>(
        x, gate_t, up_t, nullptr, counts, elist, wlist);

    // Routed down -> dout
    mma_down<true><<<dim3(C_DIM / 128, CAP / 128, E_NUM), 512>>>(
        hidden, down_t, dout, H_DIM, counts);

    // Shared gate/up -> hs
    mma_gateup<false><<<dim3(HS_DIM / 128, S_TOK / 128), 512>>>(
        x, sgw, suw, hs, nullptr, nullptr, nullptr);

    // Shared down -> out
    mma_down<false><<<dim3(C_DIM / 128, S_TOK / 128), 512>>>(
        hs, sdw, out, HS_DIM, nullptr);

    // Combine routed into out
    combine_kernel<<<S_TOK, 256>>>(tok_e, tok_pos, dout, out);
}